// round 1
// baseline (speedup 1.0000x reference)
#include <cuda_runtime.h>
#include <math.h>

// Problem constants (fixed shapes per reference)
#define N_VN   8000
#define N_CN   4000
#define DV     3
#define DC     6
#define BATCH  1250
#define BP     1280          // padded batch stride (128B aligned rows)
#define NEDGE  (DV * N_VN)   // 24000
#define NUM_ITER 5
#define LLR_MAXF 20.0f

// Output layout: [c (B*n zeros)][c_hat (B*n)][llr (B*n)][loss (1)]
#define OUT_CHAT  ((size_t)BATCH * N_VN)
#define OUT_LLR   ((size_t)2 * BATCH * N_VN)
#define OUT_LOSS  ((size_t)3 * BATCH * N_VN)

// Scratch (device globals; no allocation allowed)
__device__ float g_L[(size_t)N_VN * BP];          // 40 MB  L[v][b]
__device__ float g_msg_vn[(size_t)NEDGE * BP];    // 120 MB msg_vn[e][b]
__device__ float g_msg_cn[(size_t)NEDGE * BP];    // 120 MB msg_cn[e][b]
__device__ float g_xtot[(size_t)N_VN * BP];       // 40 MB  x_tot[v][b] (last iter)
__device__ int   g_cn_edges[NEDGE];               // CSR: 6 edges per CN
__device__ int   g_cn_cnt[N_CN];
__device__ double g_loss;

// ---------------------------------------------------------------------------
__global__ void zero_misc_kernel() {
    int i = blockIdx.x * blockDim.x + threadIdx.x;
    if (i < N_CN) g_cn_cnt[i] = 0;
    if (i == 0) g_loss = 0.0;
}

// ---------------------------------------------------------------------------
// Init: compute llr output (coalesced), transpose to L[v][b], init msg_vn.
__global__ void init_kernel(const float* __restrict__ noise,
                            const int* __restrict__ ebno_p,
                            float* __restrict__ out) {
    __shared__ float tile[32][33];

    // sigma2 = 4 / no, no = 1/(10^(ebno/10) * 0.5)  =>  sigma2 = 2*10^(ebno/10)
    int iv = ebno_p[0];
    float eb = (iv >= -100 && iv <= 100) ? (float)iv : __int_as_float(iv);
    float sigma2 = 2.0f * exp10f(eb * 0.1f);
    float half_s2 = 0.5f * sigma2;
    float sq = sqrtf(sigma2);

    int v = blockIdx.x * 32 + threadIdx.x;   // 250 tiles * 32 == 8000 exact
    int b = blockIdx.y * 32 + threadIdx.y;

    float Lval = 0.0f;
    if (b < BATCH) {
        float nz = noise[(size_t)b * N_VN + v];
        float llr = -half_s2 + sq * nz;
        out[OUT_LLR + (size_t)b * N_VN + v] = llr;   // coalesced
        Lval = -llr;                                 // L = -llr.T
    }
    tile[threadIdx.y][threadIdx.x] = Lval;
    __syncthreads();

    int v2 = blockIdx.x * 32 + threadIdx.y;
    int b2 = blockIdx.y * 32 + threadIdx.x;
    if (b2 < BATCH) {
        float val = tile[threadIdx.x][threadIdx.y];
        size_t base = (size_t)v2 * BP + b2;
        g_L[base] = val;
        g_msg_vn[base] = val;                              // edge v
        g_msg_vn[(size_t)N_VN * BP + base] = val;          // edge v+N_VN
        g_msg_vn[(size_t)2 * N_VN * BP + base] = val;      // edge v+2*N_VN
    }
}

// ---------------------------------------------------------------------------
__global__ void build_csr_kernel(const int* __restrict__ cn_idx) {
    int e = blockIdx.x * blockDim.x + threadIdx.x;
    if (e < NEDGE) {
        int c = cn_idx[e];
        int s = atomicAdd(&g_cn_cnt[c], 1);
        g_cn_edges[c * DC + s] = e;   // order within CN is irrelevant (exclusive combine)
    }
}

// ---------------------------------------------------------------------------
// CN update: per (cn, batch) thread, degree-6 exclusive tanh-product in log domain.
__global__ __launch_bounds__(256) void cn_kernel(const float* __restrict__ weights) {
    __shared__ int   se[DC];
    __shared__ float sw[DC];
    int c = blockIdx.x;
    if (threadIdx.x < DC) {
        int e = g_cn_edges[c * DC + threadIdx.x];
        se[threadIdx.x] = e;
        sw[threadIdx.x] = weights[e];
    }
    __syncthreads();

    int b = blockIdx.y * blockDim.x + threadIdx.x;
    if (b >= BATCH) return;

    float lg[DC];
    int   neg[DC];
    float sumlog = 0.0f;
    int   negsum = 0;
#pragma unroll
    for (int j = 0; j < DC; j++) {
        float m = g_msg_vn[(size_t)se[j] * BP + b] * sw[j];
        m = fminf(fmaxf(m, -LLR_MAXF), LLR_MAXF);
        float t = tanhf(0.5f * m);
        neg[j] = (t < 0.0f) ? 1 : 0;
        lg[j] = logf(fmaxf(fabsf(t), 1e-12f));
        sumlog += lg[j];
        negsum += neg[j];
    }
#pragma unroll
    for (int j = 0; j < DC; j++) {
        float mag = expf(sumlog - lg[j]);
        float sgn = ((negsum - neg[j]) & 1) ? -1.0f : 1.0f;
        float prod = sgn * mag;
        prod = fminf(fmaxf(prod, -1.0f + 1e-7f), 1.0f - 1e-7f);
        g_msg_cn[(size_t)se[j] * BP + b] = 2.0f * atanhf(prod);
    }
}

// ---------------------------------------------------------------------------
// VN update: x_tot = L + sum(msg_cn), msg_vn = x_tot - msg_cn, loss += softplus(-x_tot)
__global__ __launch_bounds__(256) void vn_kernel(int last) {
    int v = blockIdx.x;
    int b = blockIdx.y * blockDim.x + threadIdx.x;

    float sp = 0.0f;
    if (b < BATCH) {
        size_t base = (size_t)v * BP + b;
        float c0 = g_msg_cn[base];
        float c1 = g_msg_cn[(size_t)N_VN * BP + base];
        float c2 = g_msg_cn[(size_t)2 * N_VN * BP + base];
        float x = g_L[base] + (c0 + c1 + c2);
        g_msg_vn[base] = x - c0;
        g_msg_vn[(size_t)N_VN * BP + base] = x - c1;
        g_msg_vn[(size_t)2 * N_VN * BP + base] = x - c2;
        float ch = -x;
        // softplus(ch) = max(ch,0) + log1p(exp(-|ch|))
        sp = fmaxf(ch, 0.0f) + log1pf(expf(-fabsf(ch)));
        if (last) g_xtot[base] = x;
    }

    __shared__ float red[256];
    red[threadIdx.x] = sp;
    __syncthreads();
    for (int s = 128; s > 0; s >>= 1) {
        if (threadIdx.x < s) red[threadIdx.x] += red[threadIdx.x + s];
        __syncthreads();
    }
    if (threadIdx.x == 0) atomicAdd(&g_loss, (double)red[0]);
}

// ---------------------------------------------------------------------------
// c_hat = -x_tot.T, tiled transpose for coalesced writes
__global__ void chat_kernel(float* __restrict__ out) {
    __shared__ float tile[32][33];
    int v = blockIdx.x * 32 + threadIdx.x;   // read phase: b slow, v fast? no:
    // read g_xtot[v][b] coalesced in b:
    int vr = blockIdx.x * 32 + threadIdx.y;
    int br = blockIdx.y * 32 + threadIdx.x;
    float val = 0.0f;
    if (br < BATCH) val = g_xtot[(size_t)vr * BP + br];
    tile[threadIdx.y][threadIdx.x] = val;
    __syncthreads();
    int vw = blockIdx.x * 32 + threadIdx.x;
    int bw = blockIdx.y * 32 + threadIdx.y;
    (void)v;
    if (bw < BATCH) {
        out[OUT_CHAT + (size_t)bw * N_VN + vw] = -tile[threadIdx.x][threadIdx.y];
    }
}

// ---------------------------------------------------------------------------
__global__ void loss_kernel(float* __restrict__ out) {
    if (threadIdx.x == 0 && blockIdx.x == 0) {
        double denom = (double)NUM_ITER * (double)BATCH * (double)N_VN;
        out[OUT_LOSS] = (float)(g_loss / denom);
    }
}

// ---------------------------------------------------------------------------
extern "C" void kernel_launch(void* const* d_in, const int* in_sizes, int n_in,
                              void* d_out, int out_size) {
    const float* noise   = (const float*)d_in[0];
    const float* weights = (const float*)d_in[1];
    // d_in[2] = vn_idx (structure is tile(arange(N_VN), DV) by construction; implicit)
    const int*   cn_idx  = (const int*)d_in[3];
    const int*   ebno    = (const int*)d_in[4];
    float* out = (float*)d_out;

    // c output = zeros
    cudaMemsetAsync(out, 0, (size_t)BATCH * N_VN * sizeof(float));

    zero_misc_kernel<<<(N_CN + 255) / 256, 256>>>();

    dim3 tb(32, 32);
    dim3 tg(N_VN / 32, (BATCH + 31) / 32);   // 250 x 40
    init_kernel<<<tg, tb>>>(noise, ebno, out);

    build_csr_kernel<<<(NEDGE + 255) / 256, 256>>>(cn_idx);

    const int BCH = (BATCH + 255) / 256;     // 5 batch chunks
    for (int it = 0; it < NUM_ITER; it++) {
        cn_kernel<<<dim3(N_CN, BCH), 256>>>(weights);
        vn_kernel<<<dim3(N_VN, BCH), 256>>>(it == NUM_ITER - 1 ? 1 : 0);
    }

    chat_kernel<<<tg, tb>>>(out);
    loss_kernel<<<1, 32>>>(out);
}

// round 2
// speedup vs baseline: 2.0257x; 2.0257x over previous
#include <cuda_runtime.h>
#include <math.h>

// Problem constants (fixed shapes per reference)
#define N_VN   8000
#define N_CN   4000
#define DV     3
#define DC     6
#define BATCH  1250
#define BP     1280          // padded batch stride (128B aligned rows)
#define BP4    (BP/4)        // 320 float4 lanes
#define NEDGE  (DV * N_VN)   // 24000
#define NUM_ITER 5
#define LLR_MAXF 20.0f

// Output layout: [c (B*n zeros)][c_hat (B*n)][llr (B*n)][loss (1)]
#define OUT_CHAT  ((size_t)BATCH * N_VN)
#define OUT_LLR   ((size_t)2 * BATCH * N_VN)
#define OUT_LOSS  ((size_t)3 * BATCH * N_VN)

// Scratch (device globals; no allocation allowed)
__device__ float g_L[(size_t)N_VN * BP];          // 40 MB  L[v][b]
__device__ float g_xtot[(size_t)N_VN * BP];       // 40 MB  x_tot[v][b] (doubles as msg_vn source)
__device__ float g_msg_cn[(size_t)NEDGE * BP];    // 120 MB msg_cn[e][b]
__device__ int   g_cn_edges[NEDGE];               // CSR: 6 edges per CN
__device__ int   g_cn_cnt[N_CN];
__device__ double g_loss;

// ---------------------------------------------------------------------------
__global__ void zero_misc_kernel() {
    int i = blockIdx.x * blockDim.x + threadIdx.x;
    if (i < N_CN) g_cn_cnt[i] = 0;
    if (i == 0) g_loss = 0.0;
}

// ---------------------------------------------------------------------------
// Init: llr output (coalesced), transpose to L[v][b], x_tot = L (first msg_vn).
// Padded batch columns [1250,1280) get zeros so later kernels can run unmasked.
__global__ void init_kernel(const float* __restrict__ noise,
                            const int* __restrict__ ebno_p,
                            float* __restrict__ out) {
    __shared__ float tile[32][33];

    // sigma2 = 4 / no, no = 1/(10^(ebno/10) * 0.5)  =>  sigma2 = 2*10^(ebno/10)
    int iv = ebno_p[0];
    float eb = (iv >= -100 && iv <= 100) ? (float)iv : __int_as_float(iv);
    float sigma2 = 2.0f * exp10f(eb * 0.1f);
    float half_s2 = 0.5f * sigma2;
    float sq = sqrtf(sigma2);

    int v = blockIdx.x * 32 + threadIdx.x;   // 250 tiles * 32 == 8000 exact
    int b = blockIdx.y * 32 + threadIdx.y;

    float Lval = 0.0f;
    if (b < BATCH) {
        float nz = noise[(size_t)b * N_VN + v];
        float llr = -half_s2 + sq * nz;
        out[OUT_LLR + (size_t)b * N_VN + v] = llr;   // coalesced
        Lval = -llr;                                 // L = -llr.T
    }
    tile[threadIdx.y][threadIdx.x] = Lval;
    __syncthreads();

    int v2 = blockIdx.x * 32 + threadIdx.y;
    int b2 = blockIdx.y * 32 + threadIdx.x;
    if (b2 < BP) {
        float val = tile[threadIdx.x][threadIdx.y];  // 0 in padding
        size_t base = (size_t)v2 * BP + b2;
        g_L[base] = val;
        g_xtot[base] = val;
    }
}

// ---------------------------------------------------------------------------
__global__ void build_csr_kernel(const int* __restrict__ cn_idx) {
    int e = blockIdx.x * blockDim.x + threadIdx.x;
    if (e < NEDGE) {
        int c = cn_idx[e];
        int s = atomicAdd(&g_cn_cnt[c], 1);
        g_cn_edges[c * DC + s] = e;   // order within CN is irrelevant (exclusive product)
    }
}

// ---------------------------------------------------------------------------
// CN update, float4 over batch.
// msg_vn[e] = x_tot[vn(e)] - msg_cn_prev[e]   (exactly reference's update)
// t_j = tanh(clip(w*msg_vn)/2) signed, |t| clamped >= 1e-12 (sign of 0 -> +)
// exclusive signed product via prefix/suffix, msg = log((1+p)/(1-p)).
__global__ __launch_bounds__(BP4) void cn_kernel(const float* __restrict__ weights,
                                                 int first) {
    __shared__ int   sv[DC];     // vn row of edge
    __shared__ int   se[DC];     // edge id
    __shared__ float sw[DC];
    int c = blockIdx.x;
    if (threadIdx.x < DC) {
        int e = g_cn_edges[c * DC + threadIdx.x];
        se[threadIdx.x] = e;
        sv[threadIdx.x] = e % N_VN;   // vn_idx = tile(arange(N_VN), DV)
        sw[threadIdx.x] = weights[e];
    }
    __syncthreads();

    size_t boff = (size_t)threadIdx.x * 4;   // 0..1276

    float4 t[DC];
#pragma unroll
    for (int j = 0; j < DC; j++) {
        const float4 x = *(const float4*)(g_xtot + (size_t)sv[j] * BP + boff);
        float4 mc = make_float4(0.f, 0.f, 0.f, 0.f);
        if (!first) mc = *(const float4*)(g_msg_cn + (size_t)se[j] * BP + boff);
        float w = sw[j];
#pragma unroll
        for (int k = 0; k < 4; k++) {
            float m = ((&x.x)[k] - (&mc.x)[k]) * w;
            m = fminf(fmaxf(m, -LLR_MAXF), LLR_MAXF);
            float e = __expf(-m);
            float tv = __fdividef(1.0f - e, 1.0f + e);      // tanh(m/2)
            float at = fmaxf(fabsf(tv), 1e-12f);
            (&t[j].x)[k] = (tv < 0.0f) ? -at : at;
        }
    }

    // prefix products
    float4 pre[DC];
    pre[0] = make_float4(1.f, 1.f, 1.f, 1.f);
#pragma unroll
    for (int j = 1; j < DC; j++) {
#pragma unroll
        for (int k = 0; k < 4; k++)
            (&pre[j].x)[k] = (&pre[j-1].x)[k] * (&t[j-1].x)[k];
    }

    // suffix sweep: p_j = pre_j * suf, then suf *= t_j
    float4 suf = make_float4(1.f, 1.f, 1.f, 1.f);
#pragma unroll
    for (int j = DC - 1; j >= 0; j--) {
        float4 msg;
#pragma unroll
        for (int k = 0; k < 4; k++) {
            float p = (&pre[j].x)[k] * (&suf.x)[k];
            p = fminf(fmaxf(p, -1.0f + 1e-7f), 1.0f - 1e-7f);
            (&msg.x)[k] = __logf(__fdividef(1.0f + p, 1.0f - p));   // 2*atanh(p)
            (&suf.x)[k] = (&suf.x)[k] * (&t[j].x)[k];
        }
        *(float4*)(g_msg_cn + (size_t)se[j] * BP + boff) = msg;
    }
}

// ---------------------------------------------------------------------------
// VN update: x_tot = L + sum_dv(msg_cn); loss += softplus(-x_tot) (valid b only)
__global__ __launch_bounds__(BP4) void vn_kernel() {
    int v = blockIdx.x;
    size_t base = (size_t)v * BP + (size_t)threadIdx.x * 4;

    const float4 c0 = *(const float4*)(g_msg_cn + base);
    const float4 c1 = *(const float4*)(g_msg_cn + (size_t)N_VN * BP + base);
    const float4 c2 = *(const float4*)(g_msg_cn + (size_t)2 * N_VN * BP + base);
    const float4 Lv = *(const float4*)(g_L + base);

    float4 x;
    float sp = 0.0f;
    int b0 = threadIdx.x * 4;
#pragma unroll
    for (int k = 0; k < 4; k++) {
        float xv = (&Lv.x)[k] + (((&c0.x)[k] + (&c1.x)[k]) + (&c2.x)[k]);
        (&x.x)[k] = xv;
        if (b0 + k < BATCH) {
            float ch = -xv;
            // softplus(ch) = max(ch,0) + log(1 + exp(-|ch|))
            sp += fmaxf(ch, 0.0f) + __logf(1.0f + __expf(-fabsf(ch)));
        }
    }
    *(float4*)(g_xtot + base) = x;

    // warp reduce then 1 atomic per block
    for (int o = 16; o > 0; o >>= 1)
        sp += __shfl_down_sync(0xffffffffu, sp, o);
    __shared__ float red[BP4 / 32];
    if ((threadIdx.x & 31) == 0) red[threadIdx.x >> 5] = sp;
    __syncthreads();
    if (threadIdx.x == 0) {
        float s = 0.0f;
#pragma unroll
        for (int w = 0; w < BP4 / 32; w++) s += red[w];
        atomicAdd(&g_loss, (double)s);
    }
}

// ---------------------------------------------------------------------------
// c_hat = -x_tot.T, tiled transpose for coalesced writes
__global__ void chat_kernel(float* __restrict__ out) {
    __shared__ float tile[32][33];
    int vr = blockIdx.x * 32 + threadIdx.y;
    int br = blockIdx.y * 32 + threadIdx.x;
    float val = 0.0f;
    if (br < BATCH) val = g_xtot[(size_t)vr * BP + br];
    tile[threadIdx.y][threadIdx.x] = val;
    __syncthreads();
    int vw = blockIdx.x * 32 + threadIdx.x;
    int bw = blockIdx.y * 32 + threadIdx.y;
    if (bw < BATCH) {
        out[OUT_CHAT + (size_t)bw * N_VN + vw] = -tile[threadIdx.x][threadIdx.y];
    }
}

// ---------------------------------------------------------------------------
__global__ void loss_kernel(float* __restrict__ out) {
    if (threadIdx.x == 0 && blockIdx.x == 0) {
        double denom = (double)NUM_ITER * (double)BATCH * (double)N_VN;
        out[OUT_LOSS] = (float)(g_loss / denom);
    }
}

// ---------------------------------------------------------------------------
extern "C" void kernel_launch(void* const* d_in, const int* in_sizes, int n_in,
                              void* d_out, int out_size) {
    const float* noise   = (const float*)d_in[0];
    const float* weights = (const float*)d_in[1];
    // d_in[2] = vn_idx (tile(arange(N_VN), DV) by construction; implicit)
    const int*   cn_idx  = (const int*)d_in[3];
    const int*   ebno    = (const int*)d_in[4];
    float* out = (float*)d_out;

    // c output = zeros
    cudaMemsetAsync(out, 0, (size_t)BATCH * N_VN * sizeof(float));

    zero_misc_kernel<<<(N_CN + 255) / 256, 256>>>();

    dim3 tb(32, 32);
    dim3 tg(N_VN / 32, (BATCH + 31) / 32);   // 250 x 40
    init_kernel<<<tg, tb>>>(noise, ebno, out);

    build_csr_kernel<<<(NEDGE + 255) / 256, 256>>>(cn_idx);

    for (int it = 0; it < NUM_ITER; it++) {
        cn_kernel<<<N_CN, BP4>>>(weights, it == 0 ? 1 : 0);
        vn_kernel<<<N_VN, BP4>>>();
    }

    chat_kernel<<<tg, tb>>>(out);
    loss_kernel<<<1, 32>>>(out);
}

// round 3
// speedup vs baseline: 2.5570x; 1.2623x over previous
#include <cuda_runtime.h>
#include <cuda_fp16.h>
#include <math.h>

// Problem constants (fixed shapes per reference)
#define N_VN   8000
#define N_CN   4000
#define DV     3
#define DC     6
#define BATCH  1250
#define BP     1280          // padded batch stride (128B aligned rows)
#define BP4    (BP/4)        // 320 4-wide lanes
#define NEDGE  (DV * N_VN)   // 24000
#define NUM_ITER 5

// Output layout: [c (B*n zeros)][c_hat (B*n)][llr (B*n)][loss (1)]
#define OUT_CHAT  ((size_t)BATCH * N_VN)
#define OUT_LLR   ((size_t)2 * BATCH * N_VN)
#define OUT_LOSS  ((size_t)3 * BATCH * N_VN)

struct alignas(8) h4 { __half2 a, b; };

// Scratch (device globals; no allocation allowed)
__device__ float  g_L[(size_t)N_VN * BP];          // 40 MB  L[v][b]
__device__ float  g_xtot[(size_t)N_VN * BP];       // 40 MB  x_tot[v][b]
__device__ __half g_msg_cn[(size_t)NEDGE * BP];    // 60 MB  msg_cn[e][b] fp16
__device__ int    g_cn_edges[NEDGE];               // CSR: 6 edges per CN
__device__ int    g_cn_cnt[N_CN];
__device__ double g_loss;

__device__ __forceinline__ float tanh_approx(float x) {
    float r;
    asm("tanh.approx.f32 %0, %1;" : "=f"(r) : "f"(x));
    return r;
}

// ---------------------------------------------------------------------------
__global__ void zero_misc_kernel() {
    int i = blockIdx.x * blockDim.x + threadIdx.x;
    if (i < N_CN) g_cn_cnt[i] = 0;
    if (i == 0) g_loss = 0.0;
}

// ---------------------------------------------------------------------------
// Init: llr output (coalesced), transpose to L[v][b], x_tot = L (first msg_vn).
// Padded batch columns [1250,1280) get zeros so later kernels run unmasked.
__global__ void init_kernel(const float* __restrict__ noise,
                            const int* __restrict__ ebno_p,
                            float* __restrict__ out) {
    __shared__ float tile[32][33];

    // sigma2 = 4/no, no = 1/(10^(ebno/10)*0.5)  =>  sigma2 = 2*10^(ebno/10)
    int iv = ebno_p[0];
    float eb = (iv >= -100 && iv <= 100) ? (float)iv : __int_as_float(iv);
    float sigma2 = 2.0f * exp10f(eb * 0.1f);
    float half_s2 = 0.5f * sigma2;
    float sq = sqrtf(sigma2);

    int v = blockIdx.x * 32 + threadIdx.x;   // 250 tiles * 32 == 8000 exact
    int b = blockIdx.y * 32 + threadIdx.y;

    float Lval = 0.0f;
    if (b < BATCH) {
        float nz = noise[(size_t)b * N_VN + v];
        float llr = -half_s2 + sq * nz;
        out[OUT_LLR + (size_t)b * N_VN + v] = llr;   // coalesced
        Lval = -llr;                                 // L = -llr.T
    }
    tile[threadIdx.y][threadIdx.x] = Lval;
    __syncthreads();

    int v2 = blockIdx.x * 32 + threadIdx.y;
    int b2 = blockIdx.y * 32 + threadIdx.x;
    if (b2 < BP) {
        float val = tile[threadIdx.x][threadIdx.y];  // 0 in padding
        size_t base = (size_t)v2 * BP + b2;
        g_L[base] = val;
        g_xtot[base] = val;
    }
}

// ---------------------------------------------------------------------------
__global__ void build_csr_kernel(const int* __restrict__ cn_idx) {
    int e = blockIdx.x * blockDim.x + threadIdx.x;
    if (e < NEDGE) {
        int c = cn_idx[e];
        int s = atomicAdd(&g_cn_cnt[c], 1);
        g_cn_edges[c * DC + s] = e;   // order within CN is irrelevant (exclusive product)
    }
}

// ---------------------------------------------------------------------------
// CN update, 4 batch lanes / thread.
// msg_vn[e] = x_tot[vn(e)] - msg_cn_prev[e]
// t_j = tanh(clip(msg_vn*(w/2), +-10))      (== tanh(clip(msg_vn*w,+-20)/2))
// exclusive signed product via prefix/suffix, msg = log((1+p)/(1-p)).
__global__ __launch_bounds__(BP4) void cn_kernel(const float* __restrict__ weights,
                                                 int first) {
    __shared__ int   sv[DC];     // vn row of edge
    __shared__ int   se[DC];     // edge id
    __shared__ float sw2[DC];    // w/2
    int c = blockIdx.x;
    if (threadIdx.x < DC) {
        int e = g_cn_edges[c * DC + threadIdx.x];
        se[threadIdx.x] = e;
        sv[threadIdx.x] = e % N_VN;   // vn_idx = tile(arange(N_VN), DV)
        sw2[threadIdx.x] = 0.5f * weights[e];
    }
    __syncthreads();

    size_t boff = (size_t)threadIdx.x * 4;   // 0..1276

    float4 t[DC];
#pragma unroll
    for (int j = 0; j < DC; j++) {
        const float4 x = *(const float4*)(g_xtot + (size_t)sv[j] * BP + boff);
        float4 mc = make_float4(0.f, 0.f, 0.f, 0.f);
        if (!first) {
            h4 h = *(const h4*)(g_msg_cn + (size_t)se[j] * BP + boff);
            float2 f0 = __half22float2(h.a);
            float2 f1 = __half22float2(h.b);
            mc = make_float4(f0.x, f0.y, f1.x, f1.y);
        }
        float w2 = sw2[j];
#pragma unroll
        for (int k = 0; k < 4; k++) {
            float m = ((&x.x)[k] - (&mc.x)[k]) * w2;
            m = fminf(fmaxf(m, -10.0f), 10.0f);
            (&t[j].x)[k] = tanh_approx(m);
        }
    }

    // prefix products
    float4 pre[DC];
    pre[0] = make_float4(1.f, 1.f, 1.f, 1.f);
#pragma unroll
    for (int j = 1; j < DC; j++) {
#pragma unroll
        for (int k = 0; k < 4; k++)
            (&pre[j].x)[k] = (&pre[j-1].x)[k] * (&t[j-1].x)[k];
    }

    // suffix sweep: p_j = pre_j * suf, then suf *= t_j
    float4 suf = make_float4(1.f, 1.f, 1.f, 1.f);
#pragma unroll
    for (int j = DC - 1; j >= 0; j--) {
        float4 msg;
#pragma unroll
        for (int k = 0; k < 4; k++) {
            float p = (&pre[j].x)[k] * (&suf.x)[k];
            p = fminf(fmaxf(p, -1.0f + 1e-7f), 1.0f - 1e-7f);
            (&msg.x)[k] = __logf(__fdividef(1.0f + p, 1.0f - p));   // 2*atanh(p)
            (&suf.x)[k] = (&suf.x)[k] * (&t[j].x)[k];
        }
        h4 h;
        h.a = __floats2half2_rn(msg.x, msg.y);
        h.b = __floats2half2_rn(msg.z, msg.w);
        *(h4*)(g_msg_cn + (size_t)se[j] * BP + boff) = h;
        (void)c;
    }
}

// ---------------------------------------------------------------------------
// VN update: x_tot = L + sum_dv(msg_cn); loss += softplus(-x_tot) (valid b only)
__global__ __launch_bounds__(BP4) void vn_kernel() {
    int v = blockIdx.x;
    size_t base = (size_t)v * BP + (size_t)threadIdx.x * 4;

    h4 h0 = *(const h4*)(g_msg_cn + base);
    h4 h1 = *(const h4*)(g_msg_cn + (size_t)N_VN * BP + base);
    h4 h2 = *(const h4*)(g_msg_cn + (size_t)2 * N_VN * BP + base);
    const float4 Lv = *(const float4*)(g_L + base);

    // sum in half2 pairs then widen
    float2 s0 = __half22float2(__hadd2(__hadd2(h0.a, h1.a), h2.a));
    float2 s1 = __half22float2(__hadd2(__hadd2(h0.b, h1.b), h2.b));

    float4 x;
    x.x = Lv.x + s0.x;  x.y = Lv.y + s0.y;
    x.z = Lv.z + s1.x;  x.w = Lv.w + s1.y;
    *(float4*)(g_xtot + base) = x;

    float sp = 0.0f;
    int b0 = threadIdx.x * 4;
#pragma unroll
    for (int k = 0; k < 4; k++) {
        if (b0 + k < BATCH) {
            float ch = -(&x.x)[k];
            // softplus(ch) = max(ch,0) + log(1 + exp(-|ch|))
            sp += fmaxf(ch, 0.0f) + __logf(1.0f + __expf(-fabsf(ch)));
        }
    }

    // warp reduce then 1 atomic per block
    for (int o = 16; o > 0; o >>= 1)
        sp += __shfl_down_sync(0xffffffffu, sp, o);
    __shared__ float red[BP4 / 32];
    if ((threadIdx.x & 31) == 0) red[threadIdx.x >> 5] = sp;
    __syncthreads();
    if (threadIdx.x == 0) {
        float s = 0.0f;
#pragma unroll
        for (int w = 0; w < BP4 / 32; w++) s += red[w];
        atomicAdd(&g_loss, (double)s);
    }
}

// ---------------------------------------------------------------------------
// c_hat = -x_tot.T, tiled transpose for coalesced writes
__global__ void chat_kernel(float* __restrict__ out) {
    __shared__ float tile[32][33];
    int vr = blockIdx.x * 32 + threadIdx.y;
    int br = blockIdx.y * 32 + threadIdx.x;
    float val = 0.0f;
    if (br < BATCH) val = g_xtot[(size_t)vr * BP + br];
    tile[threadIdx.y][threadIdx.x] = val;
    __syncthreads();
    int vw = blockIdx.x * 32 + threadIdx.x;
    int bw = blockIdx.y * 32 + threadIdx.y;
    if (bw < BATCH) {
        out[OUT_CHAT + (size_t)bw * N_VN + vw] = -tile[threadIdx.x][threadIdx.y];
    }
}

// ---------------------------------------------------------------------------
__global__ void loss_kernel(float* __restrict__ out) {
    if (threadIdx.x == 0 && blockIdx.x == 0) {
        double denom = (double)NUM_ITER * (double)BATCH * (double)N_VN;
        out[OUT_LOSS] = (float)(g_loss / denom);
    }
}

// ---------------------------------------------------------------------------
extern "C" void kernel_launch(void* const* d_in, const int* in_sizes, int n_in,
                              void* d_out, int out_size) {
    const float* noise   = (const float*)d_in[0];
    const float* weights = (const float*)d_in[1];
    // d_in[2] = vn_idx (tile(arange(N_VN), DV) by construction; implicit)
    const int*   cn_idx  = (const int*)d_in[3];
    const int*   ebno    = (const int*)d_in[4];
    float* out = (float*)d_out;

    // c output = zeros
    cudaMemsetAsync(out, 0, (size_t)BATCH * N_VN * sizeof(float));

    zero_misc_kernel<<<(N_CN + 255) / 256, 256>>>();

    dim3 tb(32, 32);
    dim3 tg(N_VN / 32, (BATCH + 31) / 32);   // 250 x 40
    init_kernel<<<tg, tb>>>(noise, ebno, out);

    build_csr_kernel<<<(NEDGE + 255) / 256, 256>>>(cn_idx);

    for (int it = 0; it < NUM_ITER; it++) {
        cn_kernel<<<N_CN, BP4>>>(weights, it == 0 ? 1 : 0);
        vn_kernel<<<N_VN, BP4>>>();
    }

    chat_kernel<<<tg, tb>>>(out);
    loss_kernel<<<1, 32>>>(out);
}

// round 4
// speedup vs baseline: 2.6391x; 1.0321x over previous
#include <cuda_runtime.h>
#include <cuda_fp16.h>
#include <math.h>

// Problem constants (fixed shapes per reference)
#define N_VN   8000
#define N_CN   4000
#define DV     3
#define DC     6
#define BATCH  1250
#define BP     1280          // padded batch stride (128B aligned rows)
#define BP4    (BP/4)        // 320 4-wide lanes
#define NEDGE  (DV * N_VN)   // 24000
#define NUM_ITER 5

// Output layout: [c (B*n zeros)][c_hat (B*n)][llr (B*n)][loss (1)]
#define OUT_CHAT  ((size_t)BATCH * N_VN)
#define OUT_LLR   ((size_t)2 * BATCH * N_VN)
#define OUT_LOSS  ((size_t)3 * BATCH * N_VN)

struct alignas(8) h4 { __half2 a, b; };

// Scratch (device globals; no allocation allowed)
__device__ float  g_L[(size_t)N_VN * BP];          // 40 MB  L[v][b]
__device__ float  g_xtot[(size_t)N_VN * BP];       // 40 MB  x_tot[v][b]
__device__ __half g_msg_cn[(size_t)NEDGE * BP];    // 60 MB  msg_cn[e][b] fp16
__device__ int    g_cn_edges[NEDGE];               // CSR: 6 edges per CN
__device__ int    g_cn_cnt[N_CN];
__device__ double g_loss;

__device__ __forceinline__ float tanh_approx(float x) {
    float r;
    asm("tanh.approx.f32 %0, %1;" : "=f"(r) : "f"(x));
    return r;
}

// ---------------------------------------------------------------------------
__global__ void zero_misc_kernel() {
    int i = blockIdx.x * blockDim.x + threadIdx.x;
    if (i < N_CN) g_cn_cnt[i] = 0;
    if (i == 0) g_loss = 0.0;
}

// ---------------------------------------------------------------------------
// Init: llr output (coalesced), transpose to L[v][b], x_tot = L (first msg_vn).
// Padded batch columns [1250,1280) get zeros so later kernels run unmasked.
__global__ void init_kernel(const float* __restrict__ noise,
                            const int* __restrict__ ebno_p,
                            float* __restrict__ out) {
    __shared__ float tile[32][33];

    // sigma2 = 4/no, no = 1/(10^(ebno/10)*0.5)  =>  sigma2 = 2*10^(ebno/10)
    int iv = ebno_p[0];
    float eb = (iv >= -100 && iv <= 100) ? (float)iv : __int_as_float(iv);
    float sigma2 = 2.0f * exp10f(eb * 0.1f);
    float half_s2 = 0.5f * sigma2;
    float sq = sqrtf(sigma2);

    int v = blockIdx.x * 32 + threadIdx.x;   // 250 tiles * 32 == 8000 exact
    int b = blockIdx.y * 32 + threadIdx.y;

    float Lval = 0.0f;
    if (b < BATCH) {
        float nz = noise[(size_t)b * N_VN + v];
        float llr = -half_s2 + sq * nz;
        out[OUT_LLR + (size_t)b * N_VN + v] = llr;   // coalesced
        Lval = -llr;                                 // L = -llr.T
    }
    tile[threadIdx.y][threadIdx.x] = Lval;
    __syncthreads();

    int v2 = blockIdx.x * 32 + threadIdx.y;
    int b2 = blockIdx.y * 32 + threadIdx.x;
    if (b2 < BP) {
        float val = tile[threadIdx.x][threadIdx.y];  // 0 in padding
        size_t base = (size_t)v2 * BP + b2;
        g_L[base] = val;
        g_xtot[base] = val;
    }
}

// ---------------------------------------------------------------------------
__global__ void build_csr_kernel(const int* __restrict__ cn_idx) {
    int e = blockIdx.x * blockDim.x + threadIdx.x;
    if (e < NEDGE) {
        int c = cn_idx[e];
        int s = atomicAdd(&g_cn_cnt[c], 1);
        g_cn_edges[c * DC + s] = e;   // order within CN is irrelevant (exclusive product)
    }
}

// ---------------------------------------------------------------------------
// CN update, 4 batch lanes / thread.
// msg_vn[e] = x_tot[vn(e)] - msg_cn_prev[e]
// t_j = tanh(msg_vn*(w/2))   (clip dropped: tanh rounds to +-1.0f beyond |arg|>=10,
//                             identical to reference's clip-at-20-then-tanh in fp32)
// exclusive signed product via split halves: A=t0t1t2, B=t3t4t5.
__global__ __launch_bounds__(BP4, 4) void cn_kernel(const float* __restrict__ weights,
                                                    int first) {
    __shared__ int   sv[DC];     // vn row of edge
    __shared__ int   se[DC];     // edge id
    __shared__ float sw2[DC];    // w/2
    int c = blockIdx.x;
    if (threadIdx.x < DC) {
        int e = g_cn_edges[c * DC + threadIdx.x];
        se[threadIdx.x] = e;
        sv[threadIdx.x] = e % N_VN;   // vn_idx = tile(arange(N_VN), DV)
        sw2[threadIdx.x] = 0.5f * weights[e];
    }
    __syncthreads();

    size_t boff = (size_t)threadIdx.x * 4;   // 0..1276

    // ---- batched load phase (MLP up) ----
    float4 x[DC];
#pragma unroll
    for (int j = 0; j < DC; j++)
        x[j] = *(const float4*)(g_xtot + (size_t)sv[j] * BP + boff);

    h4 mh[DC];
    if (!first) {
#pragma unroll
        for (int j = 0; j < DC; j++)
            mh[j] = *(const h4*)(g_msg_cn + (size_t)se[j] * BP + boff);
    }

    // ---- t_j = tanh((x - mc) * w/2), stored in-place into x ----
#pragma unroll
    for (int j = 0; j < DC; j++) {
        float w2 = sw2[j];
        float4 mc = make_float4(0.f, 0.f, 0.f, 0.f);
        if (!first) {
            float2 f0 = __half22float2(mh[j].a);
            float2 f1 = __half22float2(mh[j].b);
            mc = make_float4(f0.x, f0.y, f1.x, f1.y);
        }
#pragma unroll
        for (int k = 0; k < 4; k++)
            (&x[j].x)[k] = tanh_approx(((&x[j].x)[k] - (&mc.x)[k]) * w2);
    }

    // ---- split-half products ----
    float A[4], B[4];
#pragma unroll
    for (int k = 0; k < 4; k++) {
        A[k] = (&x[0].x)[k] * (&x[1].x)[k] * (&x[2].x)[k];
        B[k] = (&x[3].x)[k] * (&x[4].x)[k] * (&x[5].x)[k];
    }

    // exclusive product for edge j, then msg = log((1+p)/(1-p)) = 2*atanh(p)
#pragma unroll
    for (int j = 0; j < DC; j++) {
        int ja = (j < 3) ? ((j + 1) % 3)     : (3 + (j - 2) % 3);
        int jb = (j < 3) ? ((j + 2) % 3)     : (3 + (j - 1) % 3);
        float4 msg;
#pragma unroll
        for (int k = 0; k < 4; k++) {
            float other = (j < 3) ? B[k] : A[k];
            float p = (&x[ja].x)[k] * (&x[jb].x)[k] * other;
            p = fminf(fmaxf(p, -1.0f + 1e-7f), 1.0f - 1e-7f);
            (&msg.x)[k] = __logf(__fdividef(1.0f + p, 1.0f - p));
        }
        h4 h;
        h.a = __floats2half2_rn(msg.x, msg.y);
        h.b = __floats2half2_rn(msg.z, msg.w);
        *(h4*)(g_msg_cn + (size_t)se[j] * BP + boff) = h;
    }
}

// ---------------------------------------------------------------------------
// VN update: x_tot = L + sum_dv(msg_cn); loss += softplus(-x_tot) (valid b only)
// 2 VNs per 640-thread block.
__global__ __launch_bounds__(2 * BP4) void vn_kernel() {
    int v = blockIdx.x * 2 + (threadIdx.x / BP4);
    int lane = threadIdx.x % BP4;
    size_t base = (size_t)v * BP + (size_t)lane * 4;

    h4 h0 = *(const h4*)(g_msg_cn + base);
    h4 h1 = *(const h4*)(g_msg_cn + (size_t)N_VN * BP + base);
    h4 h2 = *(const h4*)(g_msg_cn + (size_t)2 * N_VN * BP + base);
    const float4 Lv = *(const float4*)(g_L + base);

    float2 s0 = __half22float2(__hadd2(__hadd2(h0.a, h1.a), h2.a));
    float2 s1 = __half22float2(__hadd2(__hadd2(h0.b, h1.b), h2.b));

    float4 x;
    x.x = Lv.x + s0.x;  x.y = Lv.y + s0.y;
    x.z = Lv.z + s1.x;  x.w = Lv.w + s1.y;
    *(float4*)(g_xtot + base) = x;

    float sp = 0.0f;
    int b0 = lane * 4;
#pragma unroll
    for (int k = 0; k < 4; k++) {
        if (b0 + k < BATCH) {
            float ch = -(&x.x)[k];
            sp += fmaxf(ch, 0.0f) + __logf(1.0f + __expf(-fabsf(ch)));
        }
    }

    // warp reduce then 1 atomic per block
    for (int o = 16; o > 0; o >>= 1)
        sp += __shfl_down_sync(0xffffffffu, sp, o);
    __shared__ float red[(2 * BP4) / 32];
    if ((threadIdx.x & 31) == 0) red[threadIdx.x >> 5] = sp;
    __syncthreads();
    if (threadIdx.x == 0) {
        float s = 0.0f;
#pragma unroll
        for (int w = 0; w < (2 * BP4) / 32; w++) s += red[w];
        atomicAdd(&g_loss, (double)s);
    }
}

// ---------------------------------------------------------------------------
// c_hat = -x_tot.T, tiled transpose for coalesced writes
__global__ void chat_kernel(float* __restrict__ out) {
    __shared__ float tile[32][33];
    int vr = blockIdx.x * 32 + threadIdx.y;
    int br = blockIdx.y * 32 + threadIdx.x;
    float val = 0.0f;
    if (br < BATCH) val = g_xtot[(size_t)vr * BP + br];
    tile[threadIdx.y][threadIdx.x] = val;
    __syncthreads();
    int vw = blockIdx.x * 32 + threadIdx.x;
    int bw = blockIdx.y * 32 + threadIdx.y;
    if (bw < BATCH) {
        out[OUT_CHAT + (size_t)bw * N_VN + vw] = -tile[threadIdx.x][threadIdx.y];
    }
}

// ---------------------------------------------------------------------------
__global__ void loss_kernel(float* __restrict__ out) {
    if (threadIdx.x == 0 && blockIdx.x == 0) {
        double denom = (double)NUM_ITER * (double)BATCH * (double)N_VN;
        out[OUT_LOSS] = (float)(g_loss / denom);
    }
}

// ---------------------------------------------------------------------------
extern "C" void kernel_launch(void* const* d_in, const int* in_sizes, int n_in,
                              void* d_out, int out_size) {
    const float* noise   = (const float*)d_in[0];
    const float* weights = (const float*)d_in[1];
    // d_in[2] = vn_idx (tile(arange(N_VN), DV) by construction; implicit)
    const int*   cn_idx  = (const int*)d_in[3];
    const int*   ebno    = (const int*)d_in[4];
    float* out = (float*)d_out;

    // c output = zeros
    cudaMemsetAsync(out, 0, (size_t)BATCH * N_VN * sizeof(float));

    zero_misc_kernel<<<(N_CN + 255) / 256, 256>>>();

    dim3 tb(32, 32);
    dim3 tg(N_VN / 32, (BATCH + 31) / 32);   // 250 x 40
    init_kernel<<<tg, tb>>>(noise, ebno, out);

    build_csr_kernel<<<(NEDGE + 255) / 256, 256>>>(cn_idx);

    for (int it = 0; it < NUM_ITER; it++) {
        cn_kernel<<<N_CN, BP4>>>(weights, it == 0 ? 1 : 0);
        vn_kernel<<<N_VN / 2, 2 * BP4>>>();
    }

    chat_kernel<<<tg, tb>>>(out);
    loss_kernel<<<1, 32>>>(out);
}